// round 7
// baseline (speedup 1.0000x reference)
#include <cuda_runtime.h>
#include <cstdint>

#define SEQ   512
#define BATCH 1024
#define INF   256
#define HID   512
#define OUTF  64
#define NB    8      // batch rows per block in phase 2

// ---------------- scratch (static device allocations; no cudaMalloc) --------
__device__ float g_cur[(size_t)SEQ * BATCH * HID];   // 1 GiB: X @ w_in.T for all t
__device__ float g_winT[INF * HID];                  // w_in  transposed [k][h]
__device__ float g_wrecT[HID * HID];                 // w_rec transposed [h'][h]
__device__ float g_woutT[HID * OUTF];                // w_out transposed [h][o]

// ---------------- setup: transposes ----------------------------------------
__global__ void setup_kernel(const float* __restrict__ w_in,
                             const float* __restrict__ w_rec,
                             const float* __restrict__ w_out) {
    int stride = gridDim.x * blockDim.x;
    int idx = blockIdx.x * blockDim.x + threadIdx.x;
    for (int i = idx; i < INF * HID; i += stride) {
        int k = i / HID, h = i % HID;
        g_winT[i] = w_in[h * INF + k];
    }
    for (int i = idx; i < HID * HID; i += stride) {
        int hp = i / HID, h = i % HID;
        g_wrecT[i] = w_rec[h * HID + hp];
    }
    for (int i = idx; i < HID * OUTF; i += stride) {
        int h = i / OUTF, o = i % OUTF;
        g_woutT[i] = w_out[o * HID + h];
    }
}

// ---------------- phase 1: C[m,h] = sum_k X[m,k] * w_in[h,k] ---------------
// fp32, strictly k-ascending single-accumulator FMA chain per output element
// (bitwise-matches cuBLAS SIMT SGEMM accumulation).
#define BM 128
#define BN 128
#define BK 8

__global__ __launch_bounds__(256) void gemm_kernel(const float* __restrict__ X) {
    __shared__ float Xs[BK][BM];
    __shared__ float Ws[BK][BN];

    const int bm = blockIdx.x;            // 0..4095
    const int bn = blockIdx.y;            // 0..3
    const int tid = threadIdx.x;
    const int tx = tid % 16;
    const int ty = tid / 16;

    const float* Xblk = X + (size_t)bm * BM * INF;
    const float* Wblk = g_winT + bn * BN;

    // load mapping
    const int lm = tid >> 1;              // 0..127
    const int lk = (tid & 1) * 4;         // 0 or 4
    const int wk = tid >> 5;              // 0..7
    const int wn = (tid & 31) * 4;        // 0..124

    float acc[8][8];
#pragma unroll
    for (int i = 0; i < 8; i++)
#pragma unroll
        for (int j = 0; j < 8; j++) acc[i][j] = 0.0f;

    for (int k0 = 0; k0 < INF; k0 += BK) {
        float4 xv = *(const float4*)(Xblk + (size_t)lm * INF + k0 + lk);
        Xs[lk + 0][lm] = xv.x;
        Xs[lk + 1][lm] = xv.y;
        Xs[lk + 2][lm] = xv.z;
        Xs[lk + 3][lm] = xv.w;
        float4 wv = *(const float4*)(Wblk + (size_t)(k0 + wk) * HID + wn);
        *(float4*)&Ws[wk][wn] = wv;
        __syncthreads();
#pragma unroll
        for (int kk = 0; kk < BK; kk++) {
            float a[8], b[8];
#pragma unroll
            for (int j = 0; j < 8; j++) a[j] = Xs[kk][ty * 8 + j];
#pragma unroll
            for (int j = 0; j < 8; j++) b[j] = Ws[kk][tx * 8 + j];
#pragma unroll
            for (int i = 0; i < 8; i++)
#pragma unroll
                for (int j = 0; j < 8; j++)
                    acc[i][j] = fmaf(a[i], b[j], acc[i][j]);
        }
        __syncthreads();
    }

    float* Cblk = g_cur + (size_t)bm * BM * HID + bn * BN;
#pragma unroll
    for (int i = 0; i < 8; i++) {
#pragma unroll
        for (int j = 0; j < 8; j += 4) {
            float4 v = make_float4(acc[i][j], acc[i][j + 1], acc[i][j + 2], acc[i][j + 3]);
            *(float4*)(Cblk + (size_t)(ty * 8 + i) * HID + tx * 8 + j) = v;
        }
    }
}

// ---------------- phase 2: sequential LIF scan ------------------------------
// One block = NB batch rows, 512 threads (one per hidden unit), loops t=0..511.
// Decay updates use fmaf (contracted mul+add), matching what ptxas -fmad=true
// does to XLA's emitted mul/add PTX in the reference's fused elementwise
// kernels. All other ops per-op rounded.
__global__ __launch_bounds__(512) void snn_kernel(float* __restrict__ out) {
    __shared__ int   s_list[2][NB][HID];
    __shared__ int   s_cnt[2][NB];
    __shared__ int   s_wcnt[NB][16];

    const int tid  = threadIdx.x;
    const int h    = tid;
    const int lane = tid & 31;
    const int warp = tid >> 5;
    const int row0 = blockIdx.x * NB;

    // readout pair: thread handles (prow, po)
    const int prow = tid >> 6;   // 0..7
    const int po   = tid & 63;   // 0..63

    float v[NB], isyn[NB];
#pragma unroll
    for (int r = 0; r < NB; r++) { v[r] = 0.0f; isyn[r] = 0.0f; }
    float vo = 0.0f, io = 0.0f;

    if (tid < 2 * NB) ((int*)s_cnt)[tid] = 0;
    __syncthreads();

    for (int t = 0; t < SEQ; t++) {
        const int oldp = t & 1;
        const int newp = oldp ^ 1;

        float zn[NB], ipart[NB];
#pragma unroll
        for (int r = 0; r < NB; r++) {
            float c  = g_cur[((size_t)t * BATCH + row0 + r) * HID + h];
            // t1 = (0 - v) + i   (two separately-rounded ops)
            float t1 = __fadd_rn(__fsub_rn(0.0f, v[r]), isyn[r]);
            // v_dec = v + 0.1*t1  -> contracted FFMA
            float vd = fmaf(0.1f, t1, v[r]);
            // i_dec = i + 0.2*(-i) -> contracted FFMA
            float id = fmaf(0.2f, -isyn[r], isyn[r]);
            // z = (v_dec - 1 > 0)
            float z  = (__fsub_rn(vd, 1.0f) > 0.0f) ? 1.0f : 0.0f;
            zn[r] = z;
            // v_new = (1-z)*v_dec + z*0   (exact for z in {0,1})
            v[r] = __fadd_rn(__fmul_rn(__fsub_rn(1.0f, z), vd), __fmul_rn(z, 0.0f));
            // (i_dec + g1)
            ipart[r] = __fadd_rn(id, c);
        }

        // build new spike lists (ascending h)
        unsigned masks[NB];
#pragma unroll
        for (int r = 0; r < NB; r++) {
            masks[r] = __ballot_sync(0xffffffffu, zn[r] != 0.0f);
            if (lane == 0) s_wcnt[r][warp] = __popc(masks[r]);
        }
        __syncthreads();   // sync1: warp counts visible
#pragma unroll
        for (int r = 0; r < NB; r++) {
            int base = 0;
#pragma unroll
            for (int w = 0; w < 16; w++) base += (w < warp) ? s_wcnt[r][w] : 0;
            if (zn[r] != 0.0f) {
                int pos = base + __popc(masks[r] & ((1u << lane) - 1u));
                s_list[newp][r][pos] = h;
            }
        }
        if (tid < NB) {
            int tot = 0;
#pragma unroll
            for (int w = 0; w < 16; w++) tot += s_wcnt[tid][w];
            s_cnt[newp][tid] = tot;
        }

        // recurrent gather with OLD spike list (valid since previous step)
#pragma unroll
        for (int r = 0; r < NB; r++) {
            float racc = 0.0f;
            const int n = s_cnt[oldp][r];
            const int* lst = s_list[oldp][r];
            int s = 0;
            for (; s + 4 <= n; s += 4) {
                int a0 = lst[s], a1 = lst[s + 1], a2 = lst[s + 2], a3 = lst[s + 3];
                float w0 = g_wrecT[a0 * HID + h];
                float w1 = g_wrecT[a1 * HID + h];
                float w2 = g_wrecT[a2 * HID + h];
                float w3 = g_wrecT[a3 * HID + h];
                racc = __fadd_rn(racc, w0);
                racc = __fadd_rn(racc, w1);
                racc = __fadd_rn(racc, w2);
                racc = __fadd_rn(racc, w3);
            }
            for (; s < n; s++) racc = __fadd_rn(racc, g_wrecT[lst[s] * HID + h]);
            // i_new = (i_dec + g1) + g2
            isyn[r] = __fadd_rn(ipart[r], racc);
        }

        __syncthreads();   // sync2: new lists + counts complete

        // readout gather with NEW spike list + LI cell
        {
            float y = 0.0f;
            const int n = s_cnt[newp][prow];
            const int* lst = s_list[newp][prow];
            int s = 0;
            for (; s + 4 <= n; s += 4) {
                int a0 = lst[s], a1 = lst[s + 1], a2 = lst[s + 2], a3 = lst[s + 3];
                float w0 = g_woutT[a0 * OUTF + po];
                float w1 = g_woutT[a1 * OUTF + po];
                float w2 = g_woutT[a2 * OUTF + po];
                float w3 = g_woutT[a3 * OUTF + po];
                y = __fadd_rn(y, w0);
                y = __fadd_rn(y, w1);
                y = __fadd_rn(y, w2);
                y = __fadd_rn(y, w3);
            }
            for (; s < n; s++) y = __fadd_rn(y, g_woutT[lst[s] * OUTF + po]);

            // t1o = (0 - vo) + io ; vo_new = vo + 0.1*t1o -> contracted FFMA
            float t1o = __fadd_rn(__fsub_rn(0.0f, vo), io);
            float von = fmaf(0.1f, t1o, vo);
            // io_dec = io + 0.2*(-io) -> contracted FFMA
            float iod = fmaf(0.2f, -io, io);
            vo = von;
            io = __fadd_rn(iod, y);

            out[((size_t)t * BATCH + row0 + prow) * OUTF + po] = vo;
        }
    }
}

// ---------------- launch -----------------------------------------------------
extern "C" void kernel_launch(void* const* d_in, const int* in_sizes, int n_in,
                              void* d_out, int out_size) {
    const float* x     = (const float*)d_in[0];   // [512,1024,256]
    const float* w_in  = (const float*)d_in[1];   // [512,256]
    const float* w_rec = (const float*)d_in[2];   // [512,512]
    const float* w_out = (const float*)d_in[3];   // [64,512]
    float* out = (float*)d_out;                   // [512,1024,64]

    setup_kernel<<<128, 256>>>(w_in, w_rec, w_out);

    dim3 ggrid((SEQ * BATCH) / BM, HID / BN);     // (4096, 4)
    gemm_kernel<<<ggrid, 256>>>(x);

    snn_kernel<<<BATCH / NB, 512>>>(out);
}

// round 8
// speedup vs baseline: 1.1667x; 1.1667x over previous
#include <cuda_runtime.h>
#include <cstdint>

#define SEQ   512
#define BATCH 1024
#define INF   256
#define HID   512
#define OUTF  64
#define NB    8      // batch rows per block in phase 2
#define NR    4      // rows per thread-subgroup (1024 threads = 2 subgroups)

// ---------------- scratch (static device allocations; no cudaMalloc) --------
__device__ float g_cur[(size_t)SEQ * BATCH * HID];   // 1 GiB: X @ w_in.T for all t
__device__ float g_winT[INF * HID];                  // w_in  transposed [k][h]
__device__ float g_wrecT[HID * HID];                 // w_rec transposed [h'][h]
__device__ float g_woutT[HID * OUTF];                // w_out transposed [h][o]

// ---------------- setup: transposes ----------------------------------------
__global__ void setup_kernel(const float* __restrict__ w_in,
                             const float* __restrict__ w_rec,
                             const float* __restrict__ w_out) {
    int stride = gridDim.x * blockDim.x;
    int idx = blockIdx.x * blockDim.x + threadIdx.x;
    for (int i = idx; i < INF * HID; i += stride) {
        int k = i / HID, h = i % HID;
        g_winT[i] = w_in[h * INF + k];
    }
    for (int i = idx; i < HID * HID; i += stride) {
        int hp = i / HID, h = i % HID;
        g_wrecT[i] = w_rec[h * HID + hp];
    }
    for (int i = idx; i < HID * OUTF; i += stride) {
        int h = i / OUTF, o = i % OUTF;
        g_woutT[i] = w_out[o * HID + h];
    }
}

// ---------------- phase 1: C[m,h] = sum_k X[m,k] * w_in[h,k] ---------------
// fp32, strictly k-ascending single-accumulator FMA chain per output element.
// Uses packed fma.rn.f32x2 (FFMA2): two independent IEEE fp32 FMAs per
// instruction -> full-rate fp32, per-lane bitwise identical to scalar fmaf.
#define BM 128
#define BN 128
#define BK 8

__device__ __forceinline__ unsigned long long dup_f32x2(float x) {
    unsigned long long d;
    asm("mov.b64 %0, {%1, %1};" : "=l"(d) : "f"(x));
    return d;
}
__device__ __forceinline__ void ffma2(unsigned long long& acc,
                                      unsigned long long a,
                                      unsigned long long b) {
    asm("fma.rn.f32x2 %0, %1, %2, %0;" : "+l"(acc) : "l"(a), "l"(b));
}

__global__ __launch_bounds__(256) void gemm_kernel(const float* __restrict__ X) {
    __shared__ float Xs[2][BK][BM];
    __shared__ float Ws[2][BK][BN];

    const int bm = blockIdx.x;            // 0..4095
    const int bn = blockIdx.y;            // 0..3
    const int tid = threadIdx.x;
    const int tx = tid % 16;
    const int ty = tid / 16;

    const float* Xblk = X + (size_t)bm * BM * INF;
    const float* Wblk = g_winT + bn * BN;

    // load mapping
    const int lm = tid >> 1;              // 0..127
    const int lk = (tid & 1) * 4;         // 0 or 4
    const int wk = tid >> 5;              // 0..7
    const int wn = (tid & 31) * 4;        // 0..124

    const int NIT = INF / BK;             // 32

    // acc2[i][j4] packs columns (2*j4, 2*j4+1) for row i
    unsigned long long acc2[8][4];
#pragma unroll
    for (int i = 0; i < 8; i++)
#pragma unroll
        for (int j = 0; j < 4; j++) acc2[i][j] = 0ull;

    // preload iter 0
    float4 xv = *(const float4*)(Xblk + (size_t)lm * INF + 0 + lk);
    float4 wv = *(const float4*)(Wblk + (size_t)(0 + wk) * HID + wn);
    Xs[0][lk + 0][lm] = xv.x;
    Xs[0][lk + 1][lm] = xv.y;
    Xs[0][lk + 2][lm] = xv.z;
    Xs[0][lk + 3][lm] = xv.w;
    *(float4*)&Ws[0][wk][wn] = wv;
    __syncthreads();

    for (int it = 0; it < NIT; it++) {
        const int cur = it & 1;
        const int nxt = cur ^ 1;
        const int k0n = (it + 1) * BK;
        if (it + 1 < NIT) {
            xv = *(const float4*)(Xblk + (size_t)lm * INF + k0n + lk);
            wv = *(const float4*)(Wblk + (size_t)(k0n + wk) * HID + wn);
        }
#pragma unroll
        for (int kk = 0; kk < BK; kk++) {
            float4 xa = *(const float4*)&Xs[cur][kk][ty * 8];
            float4 xb = *(const float4*)&Xs[cur][kk][ty * 8 + 4];
            unsigned long long a2[8];
            a2[0] = dup_f32x2(xa.x); a2[1] = dup_f32x2(xa.y);
            a2[2] = dup_f32x2(xa.z); a2[3] = dup_f32x2(xa.w);
            a2[4] = dup_f32x2(xb.x); a2[5] = dup_f32x2(xb.y);
            a2[6] = dup_f32x2(xb.z); a2[7] = dup_f32x2(xb.w);
            ulonglong2 b01 = *(const ulonglong2*)&Ws[cur][kk][tx * 8];
            ulonglong2 b23 = *(const ulonglong2*)&Ws[cur][kk][tx * 8 + 4];
            unsigned long long b2[4] = {b01.x, b01.y, b23.x, b23.y};
#pragma unroll
            for (int i = 0; i < 8; i++)
#pragma unroll
                for (int j = 0; j < 4; j++)
                    ffma2(acc2[i][j], a2[i], b2[j]);
        }
        if (it + 1 < NIT) {
            Xs[nxt][lk + 0][lm] = xv.x;
            Xs[nxt][lk + 1][lm] = xv.y;
            Xs[nxt][lk + 2][lm] = xv.z;
            Xs[nxt][lk + 3][lm] = xv.w;
            *(float4*)&Ws[nxt][wk][wn] = wv;
        }
        __syncthreads();
    }

    float* Cblk = g_cur + (size_t)bm * BM * HID + bn * BN;
#pragma unroll
    for (int i = 0; i < 8; i++) {
        // acc2[i][0..3] = 8 contiguous output floats
        *(float4*)(Cblk + (size_t)(ty * 8 + i) * HID + tx * 8)     = *(float4*)&acc2[i][0];
        *(float4*)(Cblk + (size_t)(ty * 8 + i) * HID + tx * 8 + 4) = *(float4*)&acc2[i][2];
    }
}

// ---------------- phase 2: sequential LIF scan ------------------------------
// One block = NB=8 batch rows, 1024 threads: subgroup 0 (tid<512) handles rows
// 0-3, subgroup 1 rows 4-7; each thread owns hidden unit h = tid&511 for its
// NR=4 rows. Per-(row,h) op sequence identical to the bitwise-exact R7 kernel.
// Decay updates use fmaf (contracted), matching ptxas -fmad=true on the
// reference's XLA-emitted mul/add.
__global__ __launch_bounds__(1024) void snn_kernel(float* __restrict__ out) {
    __shared__ int s_list[2][NB][HID];
    __shared__ int s_cnt[2][NB];
    __shared__ int s_wcnt[NB][16];

    const int tid  = threadIdx.x;
    const int sub  = tid >> 9;           // 0 or 1
    const int h    = tid & 511;
    const int lane = tid & 31;
    const int warp = tid >> 5;           // 0..31
    const int wsub = warp & 15;          // warp index within subgroup
    const int row0 = blockIdx.x * NB;

    // readout pair (tid < 512 only): thread handles (prow, po)
    const int prow = tid >> 6;           // 0..7
    const int po   = tid & 63;           // 0..63

    float v[NR], isyn[NR];
#pragma unroll
    for (int r = 0; r < NR; r++) { v[r] = 0.0f; isyn[r] = 0.0f; }
    float vo = 0.0f, io = 0.0f;

    if (tid < 2 * NB) ((int*)s_cnt)[tid] = 0;
    __syncthreads();

    // preload input currents for t=0
    float cc[NR];
#pragma unroll
    for (int r = 0; r < NR; r++) {
        int rg = sub * NR + r;
        cc[r] = g_cur[((size_t)0 * BATCH + row0 + rg) * HID + h];
    }

    for (int t = 0; t < SEQ; t++) {
        const int oldp = t & 1;
        const int newp = oldp ^ 1;

        float zn[NR], ipart[NR];
#pragma unroll
        for (int r = 0; r < NR; r++) {
            // t1 = (0 - v) + i   (two separately-rounded ops)
            float t1 = __fadd_rn(__fsub_rn(0.0f, v[r]), isyn[r]);
            // v_dec = v + 0.1*t1  -> contracted FFMA
            float vd = fmaf(0.1f, t1, v[r]);
            // i_dec = i + 0.2*(-i) -> contracted FFMA
            float id = fmaf(0.2f, -isyn[r], isyn[r]);
            // z = (v_dec - 1 > 0)
            float z  = (__fsub_rn(vd, 1.0f) > 0.0f) ? 1.0f : 0.0f;
            zn[r] = z;
            // v_new = (1-z)*v_dec + z*0
            v[r] = __fadd_rn(__fmul_rn(__fsub_rn(1.0f, z), vd), __fmul_rn(z, 0.0f));
            // (i_dec + g1)
            ipart[r] = __fadd_rn(id, cc[r]);
        }

        // prefetch next step's input currents (hide DRAM latency behind gathers)
        {
            const int tn = (t + 1 < SEQ) ? t + 1 : t;
#pragma unroll
            for (int r = 0; r < NR; r++) {
                int rg = sub * NR + r;
                cc[r] = g_cur[((size_t)tn * BATCH + row0 + rg) * HID + h];
            }
        }

        // build new spike lists (ascending h per row)
        unsigned masks[NR];
#pragma unroll
        for (int r = 0; r < NR; r++) {
            masks[r] = __ballot_sync(0xffffffffu, zn[r] != 0.0f);
            if (lane == 0) s_wcnt[sub * NR + r][wsub] = __popc(masks[r]);
        }
        __syncthreads();   // sync1: warp counts visible
#pragma unroll
        for (int r = 0; r < NR; r++) {
            const int rg = sub * NR + r;
            int base = 0;
#pragma unroll
            for (int w = 0; w < 16; w++) base += (w < wsub) ? s_wcnt[rg][w] : 0;
            if (zn[r] != 0.0f) {
                int pos = base + __popc(masks[r] & ((1u << lane) - 1u));
                s_list[newp][rg][pos] = h;
            }
        }
        if (tid < NB) {
            int tot = 0;
#pragma unroll
            for (int w = 0; w < 16; w++) tot += s_wcnt[tid][w];
            s_cnt[newp][tid] = tot;
        }

        // recurrent gather with OLD spike list (valid since previous step)
#pragma unroll
        for (int r = 0; r < NR; r++) {
            const int rg = sub * NR + r;
            float racc = 0.0f;
            const int n = s_cnt[oldp][rg];
            const int* lst = s_list[oldp][rg];
            int s = 0;
            for (; s + 4 <= n; s += 4) {
                int a0 = lst[s], a1 = lst[s + 1], a2 = lst[s + 2], a3 = lst[s + 3];
                float w0 = g_wrecT[a0 * HID + h];
                float w1 = g_wrecT[a1 * HID + h];
                float w2 = g_wrecT[a2 * HID + h];
                float w3 = g_wrecT[a3 * HID + h];
                racc = __fadd_rn(racc, w0);
                racc = __fadd_rn(racc, w1);
                racc = __fadd_rn(racc, w2);
                racc = __fadd_rn(racc, w3);
            }
            for (; s < n; s++) racc = __fadd_rn(racc, g_wrecT[lst[s] * HID + h]);
            // i_new = (i_dec + g1) + g2
            isyn[r] = __fadd_rn(ipart[r], racc);
        }

        __syncthreads();   // sync2: new lists + counts complete

        // readout gather with NEW spike list + LI cell (threads 0..511)
        if (tid < 512) {
            float y = 0.0f;
            const int n = s_cnt[newp][prow];
            const int* lst = s_list[newp][prow];
            int s = 0;
            for (; s + 4 <= n; s += 4) {
                int a0 = lst[s], a1 = lst[s + 1], a2 = lst[s + 2], a3 = lst[s + 3];
                float w0 = g_woutT[a0 * OUTF + po];
                float w1 = g_woutT[a1 * OUTF + po];
                float w2 = g_woutT[a2 * OUTF + po];
                float w3 = g_woutT[a3 * OUTF + po];
                y = __fadd_rn(y, w0);
                y = __fadd_rn(y, w1);
                y = __fadd_rn(y, w2);
                y = __fadd_rn(y, w3);
            }
            for (; s < n; s++) y = __fadd_rn(y, g_woutT[lst[s] * OUTF + po]);

            // t1o = (0 - vo) + io ; vo_new = vo + 0.1*t1o -> contracted FFMA
            float t1o = __fadd_rn(__fsub_rn(0.0f, vo), io);
            float von = fmaf(0.1f, t1o, vo);
            // io_dec = io + 0.2*(-io) -> contracted FFMA
            float iod = fmaf(0.2f, -io, io);
            vo = von;
            io = __fadd_rn(iod, y);

            out[((size_t)t * BATCH + row0 + prow) * OUTF + po] = vo;
        }
    }
}

// ---------------- launch -----------------------------------------------------
extern "C" void kernel_launch(void* const* d_in, const int* in_sizes, int n_in,
                              void* d_out, int out_size) {
    const float* x     = (const float*)d_in[0];   // [512,1024,256]
    const float* w_in  = (const float*)d_in[1];   // [512,256]
    const float* w_rec = (const float*)d_in[2];   // [512,512]
    const float* w_out = (const float*)d_in[3];   // [64,512]
    float* out = (float*)d_out;                   // [512,1024,64]

    setup_kernel<<<128, 256>>>(w_in, w_rec, w_out);

    dim3 ggrid((SEQ * BATCH) / BM, HID / BN);     // (4096, 4)
    gemm_kernel<<<ggrid, 256>>>(x);

    snn_kernel<<<BATCH / NB, 1024>>>(out);
}

// round 10
// speedup vs baseline: 1.2783x; 1.0957x over previous
#include <cuda_runtime.h>
#include <cstdint>

#define SEQ    512
#define BATCH  1024
#define INF    256
#define HID    512
#define OUTF   64
#define NB     8            // batch rows per scanner block
#define NPROD  160          // producer blocks
#define NSCAN  128          // scanner blocks = BATCH/NB
#define NTILES (SEQ * 32)   // per t: 8 bm-tiles x 4 bn-tiles

#define BM 128
#define BN 128
#define BK 8

// ---------------- scratch (static device allocations; no cudaMalloc) --------
__device__ float g_cur[(size_t)SEQ * BATCH * HID];   // X @ w_in.T for all t
__device__ float g_winT[INF * HID];                  // w_in  transposed [k][h]
__device__ float g_wrecT[HID * HID];                 // w_rec transposed [h'][h]
__device__ float g_woutT[HID * OUTF];                // w_out transposed [h][o]
__device__ int   g_flag[SEQ * 8];                    // per (t, bm-within-t) done count (target 4)
__device__ int   g_tilectr;                          // producer work counter

// ---------------- setup: transposes + flag reset -----------------------------
__global__ void setup_kernel(const float* __restrict__ w_in,
                             const float* __restrict__ w_rec,
                             const float* __restrict__ w_out) {
    int stride = gridDim.x * blockDim.x;
    int idx = blockIdx.x * blockDim.x + threadIdx.x;
    for (int i = idx; i < INF * HID; i += stride) {
        int k = i / HID, h = i % HID;
        g_winT[i] = w_in[h * INF + k];
    }
    for (int i = idx; i < HID * HID; i += stride) {
        int hp = i / HID, h = i % HID;
        g_wrecT[i] = w_rec[h * HID + hp];
    }
    for (int i = idx; i < HID * OUTF; i += stride) {
        int h = i / OUTF, o = i % OUTF;
        g_woutT[i] = w_out[o * HID + h];
    }
    for (int i = idx; i < SEQ * 8; i += stride) g_flag[i] = 0;
    if (idx == 0) g_tilectr = 0;
}

// ---------------- FFMA2 helpers ----------------------------------------------
__device__ __forceinline__ unsigned long long dup_f32x2(float x) {
    unsigned long long d;
    asm("mov.b64 %0, {%1, %1};" : "=l"(d) : "f"(x));
    return d;
}
__device__ __forceinline__ void ffma2(unsigned long long& acc,
                                      unsigned long long a,
                                      unsigned long long b) {
    asm("fma.rn.f32x2 %0, %1, %2, %0;" : "+l"(acc) : "l"(a), "l"(b));
}

// ---------------- producer role: GEMM tiles in ascending-t order -------------
// Exact R8 arithmetic: fp32, strictly k-ascending single-accumulator chains,
// FFMA2 (per-lane IEEE fp32), double-buffered smem. 256 threads.
__device__ void producer_body(const float* __restrict__ X, char* sraw, int tid) {
    float (*Xs)[BK][BM] = reinterpret_cast<float (*)[BK][BM]>(sraw);
    float (*Ws)[BK][BN] = reinterpret_cast<float (*)[BK][BN]>(sraw + 8192);
    int* s_tile = reinterpret_cast<int*>(sraw + 16384);

    const int tx = tid % 16;
    const int ty = tid / 16;
    const int lm = tid >> 1;              // 0..127
    const int lk = (tid & 1) * 4;         // 0 or 4
    const int wk = tid >> 5;              // 0..7
    const int wn = (tid & 31) * 4;        // 0..124
    const int NIT = INF / BK;             // 32

    for (;;) {
        if (tid == 0) *s_tile = atomicAdd(&g_tilectr, 1);
        __syncthreads();
        const int T = *s_tile;
        if (T >= NTILES) return;

        const int t   = T >> 5;
        const int rem = T & 31;
        const int bml = rem >> 2;
        const int bn  = rem & 3;
        const int bm  = t * 8 + bml;

        const float* Xblk = X + (size_t)bm * BM * INF;
        const float* Wblk = g_winT + bn * BN;

        unsigned long long acc2[8][4];
#pragma unroll
        for (int i = 0; i < 8; i++)
#pragma unroll
            for (int j = 0; j < 4; j++) acc2[i][j] = 0ull;

        // preload iter 0
        float4 xv = *(const float4*)(Xblk + (size_t)lm * INF + 0 + lk);
        float4 wv = *(const float4*)(Wblk + (size_t)(0 + wk) * HID + wn);
        Xs[0][lk + 0][lm] = xv.x;
        Xs[0][lk + 1][lm] = xv.y;
        Xs[0][lk + 2][lm] = xv.z;
        Xs[0][lk + 3][lm] = xv.w;
        *(float4*)&Ws[0][wk][wn] = wv;
        __syncthreads();

        for (int it = 0; it < NIT; it++) {
            const int cur = it & 1;
            const int nxt = cur ^ 1;
            const int k0n = (it + 1) * BK;
            if (it + 1 < NIT) {
                xv = *(const float4*)(Xblk + (size_t)lm * INF + k0n + lk);
                wv = *(const float4*)(Wblk + (size_t)(k0n + wk) * HID + wn);
            }
#pragma unroll
            for (int kk = 0; kk < BK; kk++) {
                float4 xa = *(const float4*)&Xs[cur][kk][ty * 8];
                float4 xb = *(const float4*)&Xs[cur][kk][ty * 8 + 4];
                unsigned long long a2[8];
                a2[0] = dup_f32x2(xa.x); a2[1] = dup_f32x2(xa.y);
                a2[2] = dup_f32x2(xa.z); a2[3] = dup_f32x2(xa.w);
                a2[4] = dup_f32x2(xb.x); a2[5] = dup_f32x2(xb.y);
                a2[6] = dup_f32x2(xb.z); a2[7] = dup_f32x2(xb.w);
                ulonglong2 b01 = *(const ulonglong2*)&Ws[cur][kk][tx * 8];
                ulonglong2 b23 = *(const ulonglong2*)&Ws[cur][kk][tx * 8 + 4];
                unsigned long long b2[4] = {b01.x, b01.y, b23.x, b23.y};
#pragma unroll
                for (int i = 0; i < 8; i++)
#pragma unroll
                    for (int j = 0; j < 4; j++)
                        ffma2(acc2[i][j], a2[i], b2[j]);
            }
            if (it + 1 < NIT) {
                Xs[nxt][lk + 0][lm] = xv.x;
                Xs[nxt][lk + 1][lm] = xv.y;
                Xs[nxt][lk + 2][lm] = xv.z;
                Xs[nxt][lk + 3][lm] = xv.w;
                *(float4*)&Ws[nxt][wk][wn] = wv;
            }
            __syncthreads();
        }

        float* Cblk = g_cur + (size_t)bm * BM * HID + bn * BN;
#pragma unroll
        for (int i = 0; i < 8; i++) {
            *(float4*)(Cblk + (size_t)(ty * 8 + i) * HID + tx * 8)     = *(float4*)&acc2[i][0];
            *(float4*)(Cblk + (size_t)(ty * 8 + i) * HID + tx * 8 + 4) = *(float4*)&acc2[i][2];
        }

        __threadfence();          // each thread orders its own STGs before the flag
        __syncthreads();
        if (tid == 0) atomicAdd(&g_flag[t * 8 + bml], 1);
    }
}

// ---------------- scanner role: sequential LIF scan --------------------------
// 256 threads, each owns hidden units h=tid and h=tid+256 for NB=8 rows.
// Per-(row,h) op sequence bitwise-identical to the R7/R8 passing kernel.
__device__ void scanner_body(float* __restrict__ out, char* sraw, int sb, int tid) {
    int (*s_list)[NB][HID] = reinterpret_cast<int (*)[NB][HID]>(sraw);
    int (*s_cnt)[NB]       = reinterpret_cast<int (*)[NB]>(sraw + 32768);
    int (*s_wcnt)[16]      = reinterpret_cast<int (*)[16]>(sraw + 32832);

    const int lane = tid & 31;
    const int warp = tid >> 5;           // 0..7
    const int row0 = sb * NB;
    const int prow = tid >> 5;           // 0..7 (readout row)
    const int po   = lane;               // readout cols po, po+32
    const int fbase = sb >> 4;           // bm-within-t covering this block's rows

    float v[NB][2], isyn[NB][2];
#pragma unroll
    for (int r = 0; r < NB; r++)
#pragma unroll
        for (int k = 0; k < 2; k++) { v[r][k] = 0.0f; isyn[r][k] = 0.0f; }
    float vo[2] = {0.0f, 0.0f}, io[2] = {0.0f, 0.0f};

    if (tid < 2 * NB) ((int*)s_cnt)[tid] = 0;
    __syncthreads();

    unsigned masks[NB][2];

    for (int t = 0; t < SEQ; t++) {
        const int oldp = t & 1;
        const int newp = oldp ^ 1;

        // wait until the producer finished this step's g_cur tiles (4 bn-tiles)
        if (tid == 0) {
            volatile int* f = &g_flag[t * 8 + fbase];
            while (*f < 4) __nanosleep(64);
        }
        __syncthreads();
        __threadfence();

#pragma unroll
        for (int r = 0; r < NB; r++) {
#pragma unroll
            for (int hi = 0; hi < 2; hi++) {
                const int h = tid + hi * 256;
                float c  = g_cur[((size_t)t * BATCH + row0 + r) * HID + h];
                // t1 = (0 - v) + i   (two separately-rounded ops)
                float t1 = __fadd_rn(__fsub_rn(0.0f, v[r][hi]), isyn[r][hi]);
                // v_dec = v + 0.1*t1  -> contracted FFMA
                float vd = fmaf(0.1f, t1, v[r][hi]);
                // i_dec = i + 0.2*(-i) -> contracted FFMA
                float id = fmaf(0.2f, -isyn[r][hi], isyn[r][hi]);
                // z = (v_dec - 1 > 0)
                float z  = (__fsub_rn(vd, 1.0f) > 0.0f) ? 1.0f : 0.0f;
                // v_new = (1-z)*v_dec + z*0
                v[r][hi] = __fadd_rn(__fmul_rn(__fsub_rn(1.0f, z), vd), __fmul_rn(z, 0.0f));
                // ipart = i_dec + g1 (stored in isyn until gather adds g2)
                isyn[r][hi] = __fadd_rn(id, c);
                masks[r][hi] = __ballot_sync(0xffffffffu, z != 0.0f);
                if (lane == 0) s_wcnt[r][hi * 8 + warp] = __popc(masks[r][hi]);
            }
        }
        __syncthreads();   // sync1: warp counts visible

#pragma unroll
        for (int r = 0; r < NB; r++) {
#pragma unroll
            for (int hi = 0; hi < 2; hi++) {
                const int idx = hi * 8 + warp;
                int base = 0;
#pragma unroll
                for (int j = 0; j < 16; j++) base += (j < idx) ? s_wcnt[r][j] : 0;
                if ((masks[r][hi] >> lane) & 1u) {
                    int pos = base + __popc(masks[r][hi] & ((1u << lane) - 1u));
                    s_list[newp][r][pos] = tid + hi * 256;
                }
            }
        }
        if (tid < NB) {
            int tot = 0;
#pragma unroll
            for (int j = 0; j < 16; j++) tot += s_wcnt[tid][j];
            s_cnt[newp][tid] = tot;
        }

        // recurrent gather with OLD spike list (list-ascending accumulation)
#pragma unroll
        for (int r = 0; r < NB; r++) {
            float r0 = 0.0f, r1 = 0.0f;
            const int n = s_cnt[oldp][r];
            const int* lst = s_list[oldp][r];
            int s = 0;
            for (; s + 4 <= n; s += 4) {
                int a0 = lst[s], a1 = lst[s + 1], a2 = lst[s + 2], a3 = lst[s + 3];
                float w00 = g_wrecT[a0 * HID + tid];
                float w01 = g_wrecT[a1 * HID + tid];
                float w02 = g_wrecT[a2 * HID + tid];
                float w03 = g_wrecT[a3 * HID + tid];
                float w10 = g_wrecT[a0 * HID + tid + 256];
                float w11 = g_wrecT[a1 * HID + tid + 256];
                float w12 = g_wrecT[a2 * HID + tid + 256];
                float w13 = g_wrecT[a3 * HID + tid + 256];
                r0 = __fadd_rn(r0, w00);
                r0 = __fadd_rn(r0, w01);
                r0 = __fadd_rn(r0, w02);
                r0 = __fadd_rn(r0, w03);
                r1 = __fadd_rn(r1, w10);
                r1 = __fadd_rn(r1, w11);
                r1 = __fadd_rn(r1, w12);
                r1 = __fadd_rn(r1, w13);
            }
            for (; s < n; s++) {
                int a = lst[s];
                r0 = __fadd_rn(r0, g_wrecT[a * HID + tid]);
                r1 = __fadd_rn(r1, g_wrecT[a * HID + tid + 256]);
            }
            // i_new = (i_dec + g1) + g2
            isyn[r][0] = __fadd_rn(isyn[r][0], r0);
            isyn[r][1] = __fadd_rn(isyn[r][1], r1);
        }

        __syncthreads();   // sync2: new lists + counts complete

        // readout gather with NEW spike list + LI cell (2 outputs per thread)
        {
            float y0 = 0.0f, y1 = 0.0f;
            const int n = s_cnt[newp][prow];
            const int* lst = s_list[newp][prow];
            int s = 0;
            for (; s + 4 <= n; s += 4) {
                int a0 = lst[s], a1 = lst[s + 1], a2 = lst[s + 2], a3 = lst[s + 3];
                float u00 = g_woutT[a0 * OUTF + po];
                float u01 = g_woutT[a1 * OUTF + po];
                float u02 = g_woutT[a2 * OUTF + po];
                float u03 = g_woutT[a3 * OUTF + po];
                float u10 = g_woutT[a0 * OUTF + po + 32];
                float u11 = g_woutT[a1 * OUTF + po + 32];
                float u12 = g_woutT[a2 * OUTF + po + 32];
                float u13 = g_woutT[a3 * OUTF + po + 32];
                y0 = __fadd_rn(y0, u00);
                y0 = __fadd_rn(y0, u01);
                y0 = __fadd_rn(y0, u02);
                y0 = __fadd_rn(y0, u03);
                y1 = __fadd_rn(y1, u10);
                y1 = __fadd_rn(y1, u11);
                y1 = __fadd_rn(y1, u12);
                y1 = __fadd_rn(y1, u13);
            }
            for (; s < n; s++) {
                int a = lst[s];
                y0 = __fadd_rn(y0, g_woutT[a * OUTF + po]);
                y1 = __fadd_rn(y1, g_woutT[a * OUTF + po + 32]);
            }
            float yy[2] = {y0, y1};
#pragma unroll
            for (int k = 0; k < 2; k++) {
                // t1o = (0 - vo) + io ; vo_new = vo + 0.1*t1o -> contracted FFMA
                float t1o = __fadd_rn(__fsub_rn(0.0f, vo[k]), io[k]);
                float von = fmaf(0.1f, t1o, vo[k]);
                // io_dec = io + 0.2*(-io) -> contracted FFMA
                float iod = fmaf(0.2f, -io[k], io[k]);
                vo[k] = von;
                io[k] = __fadd_rn(iod, yy[k]);
                out[((size_t)t * BATCH + row0 + prow) * OUTF + po + k * 32] = vo[k];
            }
        }
    }
}

// ---------------- fused kernel -----------------------------------------------
__global__ __launch_bounds__(256, 2) void fused_kernel(const float* __restrict__ X,
                                                       float* __restrict__ out) {
    __shared__ __align__(16) char sraw[33352];
    if (blockIdx.x < NPROD) {
        producer_body(X, sraw, threadIdx.x);
    } else {
        scanner_body(out, sraw, blockIdx.x - NPROD, threadIdx.x);
    }
}

// ---------------- launch -----------------------------------------------------
extern "C" void kernel_launch(void* const* d_in, const int* in_sizes, int n_in,
                              void* d_out, int out_size) {
    const float* x     = (const float*)d_in[0];   // [512,1024,256]
    const float* w_in  = (const float*)d_in[1];   // [512,256]
    const float* w_rec = (const float*)d_in[2];   // [512,512]
    const float* w_out = (const float*)d_in[3];   // [64,512]
    float* out = (float*)d_out;                   // [512,1024,64]

    setup_kernel<<<128, 256>>>(w_in, w_rec, w_out);
    fused_kernel<<<NPROD + NSCAN, 256>>>(x, out);
}